// round 3
// baseline (speedup 1.0000x reference)
#include <cuda_runtime.h>
#include <cuda_bf16.h>
#include <cstdint>

// Problem constants
#define BB 2
#define SS 256
#define TT 128
#define EE 512     // ES == ET == 512
#define HH 1024

// ---------------- device scratch (no allocations allowed) ----------------
__device__ float g_sL[BB * SS * HH];          // 2 MB
__device__ float g_tL[BB * TT * HH];          // 1 MB
__device__ float g_part[4 * BB * TT * SS];    // 1 MB  (4 = h-splits)

__device__ __forceinline__ float tanh_fast(float x) {
    float y;
    asm("tanh.approx.f32 %0, %1;" : "=f"(y) : "f"(x));
    return y;
}

// ---------------- projection GEMM: C[m,n] = sum_k A[m,k] * W[n,k] ----------------
// A: [M,K] row-major, W: [N,K] row-major. Tile 64x64x16, 256 threads, 4x4 microtile.
template <int DST, int M>
__global__ void gemm_nt_kernel(const float* __restrict__ A,
                               const float* __restrict__ W) {
    constexpr int K = EE;
    constexpr int N = HH;
    constexpr int BK = 16;

    __shared__ __align__(16) float As[BK][64 + 4];
    __shared__ __align__(16) float Bs[BK][64 + 4];

    float* __restrict__ C = (DST == 0) ? g_sL : g_tL;

    const int tid = threadIdx.x;
    const int tx  = tid & 15;      // n micro index
    const int ty  = tid >> 4;      // m micro index
    const int row0 = blockIdx.y * 64;
    const int col0 = blockIdx.x * 64;

    const int lk = tid & 15;       // k lane for loads
    const int lm = tid >> 4;       // row lane (16 rows/pass, 4 passes)

    float acc[4][4];
#pragma unroll
    for (int i = 0; i < 4; i++)
#pragma unroll
        for (int j = 0; j < 4; j++) acc[i][j] = 0.f;

    for (int k0 = 0; k0 < K; k0 += BK) {
#pragma unroll
        for (int p = 0; p < 4; p++) {
            int m = lm + p * 16;
            As[lk][m] = A[(size_t)(row0 + m) * K + k0 + lk];
            Bs[lk][m] = W[(size_t)(col0 + m) * K + k0 + lk];
        }
        __syncthreads();
#pragma unroll
        for (int kk = 0; kk < BK; kk++) {
            float4 a4 = *(const float4*)&As[kk][ty * 4];
            float4 b4 = *(const float4*)&Bs[kk][tx * 4];
            float av[4] = {a4.x, a4.y, a4.z, a4.w};
            float bv[4] = {b4.x, b4.y, b4.z, b4.w};
#pragma unroll
            for (int i = 0; i < 4; i++)
#pragma unroll
                for (int j = 0; j < 4; j++) acc[i][j] = fmaf(av[i], bv[j], acc[i][j]);
        }
        __syncthreads();
    }

#pragma unroll
    for (int i = 0; i < 4; i++) {
        float4 o = make_float4(acc[i][0], acc[i][1], acc[i][2], acc[i][3]);
        *(float4*)&C[(size_t)(row0 + ty * 4 + i) * N + col0 + tx * 4] = o;
    }
}

// ---------------- additive attention core (MUFU-bound) ----------------
// grid: (S/32, T/32, B*4).  Each block: 32t x 32s tile over a 256-wide h slice.
// Partial sums -> g_part[hs][b][t][s].
__global__ void attn_kernel(const float* __restrict__ Wr) {
    __shared__ __align__(16) float sSh[32][34];
    __shared__ __align__(16) float tSh[32][34];
    __shared__ float wrS[32];

    const int tid = threadIdx.x;
    const int tx = tid & 15;   // s micro (2 cols)
    const int ty = tid >> 4;   // t micro (2 rows)

    const int s0 = blockIdx.x * 32;
    const int t0 = blockIdx.y * 32;
    const int bz = blockIdx.z;
    const int b  = bz >> 2;
    const int hs = bz & 3;
    const int hbase = hs * 256;

    const int lk = tid & 31;   // h lane
    const int lr = tid >> 5;   // row lane (8 rows/pass)

    const float* __restrict__ sLb = g_sL + ((size_t)b * SS + s0) * HH;
    const float* __restrict__ tLb = g_tL + ((size_t)b * TT + t0) * HH;

    float a00 = 0.f, a01 = 0.f, a10 = 0.f, a11 = 0.f;

    for (int c = 0; c < 8; c++) {
        const int h0 = hbase + c * 32;
        if (c) __syncthreads();
#pragma unroll
        for (int p = 0; p < 4; p++) {
            int r = lr + p * 8;
            sSh[lk][r] = sLb[(size_t)r * HH + h0 + lk];
            tSh[lk][r] = tLb[(size_t)r * HH + h0 + lk];
        }
        if (tid < 32) wrS[tid] = Wr[h0 + tid];
        __syncthreads();

#pragma unroll
        for (int kk = 0; kk < 32; kk++) {
            float  w  = wrS[kk];
            float2 sv = *(const float2*)&sSh[kk][tx * 2];
            float2 tv = *(const float2*)&tSh[kk][ty * 2];
            a00 = fmaf(w, tanh_fast(tv.x + sv.x), a00);
            a01 = fmaf(w, tanh_fast(tv.x + sv.y), a01);
            a10 = fmaf(w, tanh_fast(tv.y + sv.x), a10);
            a11 = fmaf(w, tanh_fast(tv.y + sv.y), a11);
        }
    }

    const int t = t0 + ty * 2;
    const int s = s0 + tx * 2;
    float* p = g_part + (((size_t)hs * BB + b) * TT + t) * SS + s;
    *(float2*)&p[0]   = make_float2(a00, a01);
    *(float2*)&p[SS]  = make_float2(a10, a11);
}

// ---------------- reduce h-splits + bias + mask ----------------
// mask is read as float32: works for float32-encoded bools (1.0f) and for
// int32-encoded bools (bit pattern 1 -> nonzero denormal). Only ==0 means masked.
__global__ void reduce_kernel(const float* __restrict__ maskF,
                              const float* __restrict__ br,
                              float* __restrict__ out) {
    const int idx = blockIdx.x * 256 + threadIdx.x;   // [0, B*T*S)
    const int s = idx & (SS - 1);
    const int b = idx >> 15;                          // T*S = 32768 = 2^15
    float v = g_part[idx] + g_part[65536 + idx] + g_part[131072 + idx] + g_part[196608 + idx];
    bool m = __float_as_uint(maskF[b * SS + s]) != 0u;
    out[idx] = m ? (v + br[0]) : __int_as_float(0xff800000);
}

// ---------------- gate: softmax(target @ Wg^T + bg) over 2 ----------------
__global__ void gate_kernel(const float* __restrict__ tgt,
                            const float* __restrict__ Wg,
                            const float* __restrict__ bg,
                            float* __restrict__ outg) {
    const int w    = threadIdx.x >> 5;
    const int lane = threadIdx.x & 31;
    const int bt   = blockIdx.x * 8 + w;              // 32 blocks x 8 warps = 256
    const float* t = tgt + (size_t)bt * EE;
    float s0 = 0.f, s1 = 0.f;
    for (int e = lane; e < EE; e += 32) {
        float tv = t[e];
        s0 = fmaf(tv, Wg[e], s0);
        s1 = fmaf(tv, Wg[EE + e], s1);
    }
#pragma unroll
    for (int o = 16; o; o >>= 1) {
        s0 += __shfl_xor_sync(0xffffffffu, s0, o);
        s1 += __shfl_xor_sync(0xffffffffu, s1, o);
    }
    if (lane == 0) {
        float x0 = s0 + bg[0], x1 = s1 + bg[1];
        float m  = fmaxf(x0, x1);
        float e0 = expf(x0 - m), e1 = expf(x1 - m);
        float inv = 1.f / (e0 + e1);
        outg[bt * 2]     = e0 * inv;
        outg[bt * 2 + 1] = e1 * inv;
    }
}

// ---------------- launch ----------------
extern "C" void kernel_launch(void* const* d_in, const int* in_sizes, int n_in,
                              void* d_out, int out_size) {
    const float* source = (const float*)d_in[0];  // [B,S,ES]
    const float* target = (const float*)d_in[1];  // [B,T,ET]
    const float* maskF  = (const float*)d_in[2];  // [B,S] bool (promoted dtype)
    const float* Ws     = (const float*)d_in[3];  // [H,ES]
    const float* Wt     = (const float*)d_in[4];  // [H,ET]
    const float* Wr     = (const float*)d_in[5];  // [H]
    const float* br     = (const float*)d_in[6];  // scalar
    const float* Wg     = (const float*)d_in[7];  // [2,ET]
    const float* bg     = (const float*)d_in[8];  // [2]

    float* out = (float*)d_out;
    // copy_probs at out[0 .. B*T*S), gate at the tail (concat order)
    float* out_gate = out + (out_size - BB * TT * 2);

    // Projections
    gemm_nt_kernel<0, BB * SS><<<dim3(HH / 64, (BB * SS) / 64), 256>>>(source, Ws);
    gemm_nt_kernel<1, BB * TT><<<dim3(HH / 64, (BB * TT) / 64), 256>>>(target, Wt);

    // Additive attention partials
    attn_kernel<<<dim3(SS / 32, TT / 32, BB * 4), 256>>>(Wr);

    // Reduce + bias + mask
    reduce_kernel<<<(BB * TT * SS) / 256, 256>>>(maskF, br, out);

    // Gate
    gate_kernel<<<(BB * TT) / 8, 256>>>(target, Wg, bg, out_gate);
}

// round 5
// speedup vs baseline: 1.1990x; 1.1990x over previous
#include <cuda_runtime.h>
#include <cuda_bf16.h>
#include <cstdint>

// Problem constants
#define BB 2
#define SS 256
#define TT 128
#define EE 512     // ES == ET == 512
#define HH 1024

#define MROWS (BB * SS + BB * TT)   // 768 combined GEMM rows
#define GEMM_TILES ((MROWS / 32) * (HH / 64))   // 24 * 16 = 384

// ---------------- device scratch (no allocations allowed) ----------------
__device__ float g_sL[BB * SS * HH];          // 2 MB
__device__ float g_tL[BB * TT * HH];          // 1 MB

__device__ __forceinline__ float tanh_fast(float x) {
    float y;
    asm("tanh.approx.f32 %0, %1;" : "=f"(y) : "f"(x));
    return y;
}

// ---------------- combined projection GEMM + gate ----------------
// Tiles: TM=32 x TN=64, BK=16, 128 threads, 4x4 microtile, reg-prefetch.
// blocks [0, 384): GEMM.  blocks 384,385: gate softmax.
__global__ void proj_gate_kernel(const float* __restrict__ source,
                                 const float* __restrict__ target,
                                 const float* __restrict__ Ws,
                                 const float* __restrict__ Wt,
                                 const float* __restrict__ Wg,
                                 const float* __restrict__ bg,
                                 float* __restrict__ outg) {
    __shared__ __align__(16) float As[16][36];
    __shared__ __align__(16) float Bs[16][68];

    const int bx  = blockIdx.x;
    const int tid = threadIdx.x;

    if (bx >= GEMM_TILES) {
        // ---- gate: softmax over 2 of target @ Wg^T + bg ----
        const int bt = (bx - GEMM_TILES) * 128 + tid;     // 0..255
        const float4* tr = (const float4*)(target + (size_t)bt * EE);
        const float4* w0 = (const float4*)(Wg);
        const float4* w1 = (const float4*)(Wg + EE);
        float s0 = 0.f, s1 = 0.f;
#pragma unroll 8
        for (int e = 0; e < EE / 4; e++) {
            float4 t4 = tr[e];
            float4 a4 = w0[e];
            float4 b4 = w1[e];
            s0 = fmaf(t4.x, a4.x, fmaf(t4.y, a4.y, fmaf(t4.z, a4.z, fmaf(t4.w, a4.w, s0))));
            s1 = fmaf(t4.x, b4.x, fmaf(t4.y, b4.y, fmaf(t4.z, b4.z, fmaf(t4.w, b4.w, s1))));
        }
        float x0 = s0 + bg[0], x1 = s1 + bg[1];
        float m  = fmaxf(x0, x1);
        float e0 = expf(x0 - m), e1 = expf(x1 - m);
        float inv = 1.f / (e0 + e1);
        outg[bt * 2]     = e0 * inv;
        outg[bt * 2 + 1] = e1 * inv;
        return;
    }

    // ---- GEMM tile ----
    const int mt = bx >> 4;            // 0..23
    const int nt = bx & 15;            // 0..15
    const int row0 = mt * 32;          // combined row space [0,768)
    const int col0 = nt * 64;

    const float* __restrict__ A;
    const float* __restrict__ W;
    float* __restrict__ C;
    int crow0;
    if (row0 < BB * SS) { A = source + (size_t)row0 * EE; W = Ws; C = g_sL; crow0 = row0; }
    else                { A = target + (size_t)(row0 - BB * SS) * EE; W = Wt; C = g_tL; crow0 = row0 - BB * SS; }

    const int tx = tid & 15;           // n micro (tx*4)
    const int ty = tid >> 4;           // m micro (ty*4), 0..7
    const int lk = tid & 15;           // k lane
    const int lm = tid >> 4;           // 0..7

    float acc[4][4];
#pragma unroll
    for (int i = 0; i < 4; i++)
#pragma unroll
        for (int j = 0; j < 4; j++) acc[i][j] = 0.f;

    float pa[4], pb[8];
    // prefetch k-tile 0
#pragma unroll
    for (int p = 0; p < 4; p++) pa[p] = A[(size_t)(lm + 8 * p) * EE + lk];
#pragma unroll
    for (int p = 0; p < 8; p++) pb[p] = W[(size_t)(col0 + lm + 8 * p) * EE + lk];

    for (int kt = 0; kt < EE / 16; kt++) {
        if (kt) __syncthreads();
#pragma unroll
        for (int p = 0; p < 4; p++) As[lk][lm + 8 * p] = pa[p];
#pragma unroll
        for (int p = 0; p < 8; p++) Bs[lk][lm + 8 * p] = pb[p];
        __syncthreads();

        if (kt + 1 < EE / 16) {
            const int k0 = (kt + 1) * 16;
#pragma unroll
            for (int p = 0; p < 4; p++) pa[p] = A[(size_t)(lm + 8 * p) * EE + k0 + lk];
#pragma unroll
            for (int p = 0; p < 8; p++) pb[p] = W[(size_t)(col0 + lm + 8 * p) * EE + k0 + lk];
        }

#pragma unroll
        for (int kk = 0; kk < 16; kk++) {
            float4 a4 = *(const float4*)&As[kk][ty * 4];
            float4 b4 = *(const float4*)&Bs[kk][tx * 4];
            float av[4] = {a4.x, a4.y, a4.z, a4.w};
            float bv[4] = {b4.x, b4.y, b4.z, b4.w};
#pragma unroll
            for (int i = 0; i < 4; i++)
#pragma unroll
                for (int j = 0; j < 4; j++) acc[i][j] = fmaf(av[i], bv[j], acc[i][j]);
        }
    }

#pragma unroll
    for (int i = 0; i < 4; i++) {
        float4 o = make_float4(acc[i][0], acc[i][1], acc[i][2], acc[i][3]);
        *(float4*)&C[(size_t)(crow0 + ty * 4 + i) * HH + col0 + tx * 4] = o;
    }
}

// ---------------- fused additive attention (full H per block) ----------------
// grid: (S/16, T/16, B). 128 threads. Each block: 16t x 16s tile, loops over all
// 1024 h in chunks of 64, writes masked+biased output directly. MUFU-bound.
__global__ void attn_kernel(const float* __restrict__ Wr,
                            const float* __restrict__ maskF,
                            const float* __restrict__ br,
                            float* __restrict__ out) {
    __shared__ __align__(16) float sSh[64][18];
    __shared__ __align__(16) float tSh[64][18];
    __shared__ float wrS[HH];

    const int tid = threadIdx.x;
    const int tx = tid & 7;        // s-pair index (s = tx*2, tx*2+1)
    const int ty = tid >> 3;       // t index 0..15

    const int s0 = blockIdx.x * 16;
    const int t0 = blockIdx.y * 16;
    const int b  = blockIdx.z;

    // whole Wr into smem once
#pragma unroll
    for (int p = 0; p < HH / 128; p++) wrS[tid + 128 * p] = Wr[tid + 128 * p];

    const int lk = tid & 63;       // h lane within chunk
    const int lr = tid >> 6;       // 0..1

    const float* __restrict__ sLb = g_sL + ((size_t)b * SS + s0) * HH;
    const float* __restrict__ tLb = g_tL + ((size_t)b * TT + t0) * HH;

    float a0 = 0.f, a1 = 0.f;

    for (int cc = 0; cc < HH / 64; cc++) {
        const int h0 = cc * 64;
        if (cc) __syncthreads();
#pragma unroll
        for (int p = 0; p < 8; p++) {
            const int r = lr + 2 * p;
            sSh[lk][r] = sLb[(size_t)r * HH + h0 + lk];
            tSh[lk][r] = tLb[(size_t)r * HH + h0 + lk];
        }
        __syncthreads();

#pragma unroll 16
        for (int kk = 0; kk < 64; kk++) {
            float  w  = wrS[h0 + kk];
            float  tv = tSh[kk][ty];
            float2 sv = *(const float2*)&sSh[kk][tx * 2];
            a0 = fmaf(w, tanh_fast(tv + sv.x), a0);
            a1 = fmaf(w, tanh_fast(tv + sv.y), a1);
        }
    }

    const int t = t0 + ty;
    const int s = s0 + tx * 2;
    const float bias = br[0];
    const float ninf = __int_as_float(0xff800000);
    bool m0 = __float_as_uint(maskF[b * SS + s])     != 0u;
    bool m1 = __float_as_uint(maskF[b * SS + s + 1]) != 0u;
    float2 res;
    res.x = m0 ? (a0 + bias) : ninf;
    res.y = m1 ? (a1 + bias) : ninf;
    *(float2*)&out[((size_t)b * TT + t) * SS + s] = res;
}

// ---------------- launch ----------------
extern "C" void kernel_launch(void* const* d_in, const int* in_sizes, int n_in,
                              void* d_out, int out_size) {
    const float* source = (const float*)d_in[0];  // [B,S,ES]
    const float* target = (const float*)d_in[1];  // [B,T,ET]
    const float* maskF  = (const float*)d_in[2];  // [B,S] bool (promoted to f32)
    const float* Ws     = (const float*)d_in[3];  // [H,ES]
    const float* Wt     = (const float*)d_in[4];  // [H,ET]
    const float* Wr     = (const float*)d_in[5];  // [H]
    const float* br     = (const float*)d_in[6];  // scalar
    const float* Wg     = (const float*)d_in[7];  // [2,ET]
    const float* bg     = (const float*)d_in[8];  // [2]

    float* out      = (float*)d_out;
    float* out_gate = out + (out_size - BB * TT * 2);

    // Projections (both GEMMs) + gate in one launch: 384 gemm tiles + 2 gate blocks
    proj_gate_kernel<<<GEMM_TILES + 2, 128>>>(source, target, Ws, Wt, Wg, bg, out_gate);

    // Fused attention + reduce + mask + bias
    attn_kernel<<<dim3(SS / 16, TT / 16, BB), 128>>>(Wr, maskF, br, out);
}

// round 7
// speedup vs baseline: 1.3843x; 1.1546x over previous
#include <cuda_runtime.h>
#include <cuda_bf16.h>
#include <cstdint>

// Problem constants
#define BB 2
#define SS 256
#define TT 128
#define EE 512     // ES == ET == 512
#define HH 1024

#define MROWS (BB * SS + BB * TT)               // 768 combined GEMM rows
#define GEMM_TILES ((MROWS / 32) * (HH / 64))   // 24 * 16 = 384

#define NHS 8                 // h splits
#define HSP (HH / NHS)        // 128 h per split
#define OUTN (BB * TT * SS)   // 65536

// ---------------- device scratch (no allocations allowed) ----------------
__device__ float g_sL[BB * SS * HH];          // 2 MB
__device__ float g_tL[BB * TT * HH];          // 1 MB
__device__ float g_part[NHS * OUTN];          // 2 MB partials
__device__ int   g_cnt[BB * (TT / 32) * (SS / 64)];   // 32 tile counters (zero-init)

__device__ __forceinline__ float tanh_fast(float x) {
    float y;
    asm("tanh.approx.f32 %0, %1;" : "=f"(y) : "f"(x));
    return y;
}

// ---------------- combined projection GEMM + gate ----------------
__global__ void proj_gate_kernel(const float* __restrict__ source,
                                 const float* __restrict__ target,
                                 const float* __restrict__ Ws,
                                 const float* __restrict__ Wt,
                                 const float* __restrict__ Wg,
                                 const float* __restrict__ bg,
                                 float* __restrict__ outg) {
    __shared__ __align__(16) float As[16][36];
    __shared__ __align__(16) float Bs[16][68];

    const int bx  = blockIdx.x;
    const int tid = threadIdx.x;

    if (bx >= GEMM_TILES) {
        const int bt = (bx - GEMM_TILES) * 128 + tid;     // 0..255
        const float4* tr = (const float4*)(target + (size_t)bt * EE);
        const float4* w0 = (const float4*)(Wg);
        const float4* w1 = (const float4*)(Wg + EE);
        float s0 = 0.f, s1 = 0.f;
#pragma unroll 8
        for (int e = 0; e < EE / 4; e++) {
            float4 t4 = tr[e];
            float4 a4 = w0[e];
            float4 b4 = w1[e];
            s0 = fmaf(t4.x, a4.x, fmaf(t4.y, a4.y, fmaf(t4.z, a4.z, fmaf(t4.w, a4.w, s0))));
            s1 = fmaf(t4.x, b4.x, fmaf(t4.y, b4.y, fmaf(t4.z, b4.z, fmaf(t4.w, b4.w, s1))));
        }
        float x0 = s0 + bg[0], x1 = s1 + bg[1];
        float m  = fmaxf(x0, x1);
        float e0 = expf(x0 - m), e1 = expf(x1 - m);
        float inv = 1.f / (e0 + e1);
        outg[bt * 2]     = e0 * inv;
        outg[bt * 2 + 1] = e1 * inv;
        return;
    }

    const int mt = bx >> 4;
    const int nt = bx & 15;
    const int row0 = mt * 32;
    const int col0 = nt * 64;

    const float* __restrict__ A;
    const float* __restrict__ W;
    float* __restrict__ C;
    int crow0;
    if (row0 < BB * SS) { A = source + (size_t)row0 * EE; W = Ws; C = g_sL; crow0 = row0; }
    else                { A = target + (size_t)(row0 - BB * SS) * EE; W = Wt; C = g_tL; crow0 = row0 - BB * SS; }

    const int tx = tid & 15;
    const int ty = tid >> 4;
    const int lk = tid & 15;
    const int lm = tid >> 4;

    float acc[4][4];
#pragma unroll
    for (int i = 0; i < 4; i++)
#pragma unroll
        for (int j = 0; j < 4; j++) acc[i][j] = 0.f;

    float pa[4], pb[8];
#pragma unroll
    for (int p = 0; p < 4; p++) pa[p] = A[(size_t)(lm + 8 * p) * EE + lk];
#pragma unroll
    for (int p = 0; p < 8; p++) pb[p] = W[(size_t)(col0 + lm + 8 * p) * EE + lk];

    for (int kt = 0; kt < EE / 16; kt++) {
        if (kt) __syncthreads();
#pragma unroll
        for (int p = 0; p < 4; p++) As[lk][lm + 8 * p] = pa[p];
#pragma unroll
        for (int p = 0; p < 8; p++) Bs[lk][lm + 8 * p] = pb[p];
        __syncthreads();

        if (kt + 1 < EE / 16) {
            const int k0 = (kt + 1) * 16;
#pragma unroll
            for (int p = 0; p < 4; p++) pa[p] = A[(size_t)(lm + 8 * p) * EE + k0 + lk];
#pragma unroll
            for (int p = 0; p < 8; p++) pb[p] = W[(size_t)(col0 + lm + 8 * p) * EE + k0 + lk];
        }

#pragma unroll
        for (int kk = 0; kk < 16; kk++) {
            float4 a4 = *(const float4*)&As[kk][ty * 4];
            float4 b4 = *(const float4*)&Bs[kk][tx * 4];
            float av[4] = {a4.x, a4.y, a4.z, a4.w};
            float bv[4] = {b4.x, b4.y, b4.z, b4.w};
#pragma unroll
            for (int i = 0; i < 4; i++)
#pragma unroll
                for (int j = 0; j < 4; j++) acc[i][j] = fmaf(av[i], bv[j], acc[i][j]);
        }
    }

#pragma unroll
    for (int i = 0; i < 4; i++) {
        float4 o = make_float4(acc[i][0], acc[i][1], acc[i][2], acc[i][3]);
        *(float4*)&C[(size_t)(crow0 + ty * 4 + i) * HH + col0 + tx * 4] = o;
    }
}

// ---------------- additive attention: h-split + in-kernel reduce ----------------
// grid (S/64, T/32, B*NHS), 256 threads. Tile: 32t x 64s x 128h. Microtile 2t x 4s.
// Last finishing h-split block for a (b,t,s) tile sums the 8 partials, applies
// mask+bias, writes output (deterministic: fixed hs order).
__global__ void attn_kernel(const float* __restrict__ Wr,
                            const float* __restrict__ maskF,
                            const float* __restrict__ br,
                            float* __restrict__ out) {
    __shared__ float sSh[32][65];
    __shared__ float tSh[32][33];
    __shared__ float wrS[HSP];
    __shared__ int lastFlag;

    const int tid = threadIdx.x;
    const int tx = tid & 15;       // s micro: s = s0 + tx*4 .. +3
    const int ty = tid >> 4;       // t micro: t = t0 + ty*2 .. +1

    const int s0 = blockIdx.x * 64;
    const int t0 = blockIdx.y * 32;
    const int bz = blockIdx.z;
    const int b  = bz & 1;
    const int hs = bz >> 1;
    const int h0 = hs * HSP;

    if (tid < HSP) wrS[tid] = Wr[h0 + tid];

    const int lk = tid & 31;       // h lane
    const int lr = tid >> 5;       // 0..7

    const float* __restrict__ sLb = g_sL + ((size_t)b * SS + s0) * HH + h0;
    const float* __restrict__ tLb = g_tL + ((size_t)b * TT + t0) * HH + h0;

    float a[2][4];
#pragma unroll
    for (int j = 0; j < 2; j++)
#pragma unroll
        for (int i = 0; i < 4; i++) a[j][i] = 0.f;

    for (int cc = 0; cc < HSP / 32; cc++) {
        const int hc = cc * 32;
        if (cc) __syncthreads();
        // load 64 s-rows x 32 h  and 32 t-rows x 32 h (transposed into smem)
#pragma unroll
        for (int p = 0; p < 8; p++) {
            const int r = lr + 8 * p;
            sSh[lk][r] = sLb[(size_t)r * HH + hc + lk];
        }
#pragma unroll
        for (int p = 0; p < 4; p++) {
            const int r = lr + 8 * p;
            tSh[lk][r] = tLb[(size_t)r * HH + hc + lk];
        }
        __syncthreads();

#pragma unroll 8
        for (int kk = 0; kk < 32; kk++) {
            const float w  = wrS[hc + kk];
            const float t0v = tSh[kk][ty * 2];
            const float t1v = tSh[kk][ty * 2 + 1];
            float sv0 = sSh[kk][tx * 4];
            float sv1 = sSh[kk][tx * 4 + 1];
            float sv2 = sSh[kk][tx * 4 + 2];
            float sv3 = sSh[kk][tx * 4 + 3];
            a[0][0] = fmaf(w, tanh_fast(t0v + sv0), a[0][0]);
            a[0][1] = fmaf(w, tanh_fast(t0v + sv1), a[0][1]);
            a[0][2] = fmaf(w, tanh_fast(t0v + sv2), a[0][2]);
            a[0][3] = fmaf(w, tanh_fast(t0v + sv3), a[0][3]);
            a[1][0] = fmaf(w, tanh_fast(t1v + sv0), a[1][0]);
            a[1][1] = fmaf(w, tanh_fast(t1v + sv1), a[1][1]);
            a[1][2] = fmaf(w, tanh_fast(t1v + sv2), a[1][2]);
            a[1][3] = fmaf(w, tanh_fast(t1v + sv3), a[1][3]);
        }
    }

    // ---- write partials ----
    const int t = t0 + ty * 2;
    const int s = s0 + tx * 4;
    const int idx = (b * TT + t) * SS + s;
#pragma unroll
    for (int j = 0; j < 2; j++) {
        float4 o = make_float4(a[j][0], a[j][1], a[j][2], a[j][3]);
        *(float4*)&g_part[hs * OUTN + idx + j * SS] = o;
    }

    // ---- ticket: last h-split block reduces the tile ----
    __threadfence();
    __syncthreads();
    const int tile = (b * (TT / 32) + blockIdx.y) * (SS / 64) + blockIdx.x;
    if (tid == 0) lastFlag = (atomicAdd(&g_cnt[tile], 1) == NHS - 1);
    __syncthreads();
    if (!lastFlag) return;

    const float bias = br[0];
    const float ninf = __int_as_float(0xff800000);
#pragma unroll
    for (int j = 0; j < 2; j++) {
        float4 acc4 = make_float4(0.f, 0.f, 0.f, 0.f);
#pragma unroll
        for (int h = 0; h < NHS; h++) {
            const float4 p = __ldcg((const float4*)&g_part[h * OUTN + idx + j * SS]);
            acc4.x += p.x; acc4.y += p.y; acc4.z += p.z; acc4.w += p.w;
        }
        float4 res;
        res.x = (__float_as_uint(maskF[b * SS + s])     != 0u) ? (acc4.x + bias) : ninf;
        res.y = (__float_as_uint(maskF[b * SS + s + 1]) != 0u) ? (acc4.y + bias) : ninf;
        res.z = (__float_as_uint(maskF[b * SS + s + 2]) != 0u) ? (acc4.z + bias) : ninf;
        res.w = (__float_as_uint(maskF[b * SS + s + 3]) != 0u) ? (acc4.w + bias) : ninf;
        *(float4*)&out[idx + j * SS] = res;
    }
    if (tid == 0) g_cnt[tile] = 0;   // reset for next graph replay
}

// ---------------- launch ----------------
extern "C" void kernel_launch(void* const* d_in, const int* in_sizes, int n_in,
                              void* d_out, int out_size) {
    const float* source = (const float*)d_in[0];  // [B,S,ES]
    const float* target = (const float*)d_in[1];  // [B,T,ET]
    const float* maskF  = (const float*)d_in[2];  // [B,S] bool (promoted to f32)
    const float* Ws     = (const float*)d_in[3];  // [H,ES]
    const float* Wt     = (const float*)d_in[4];  // [H,ET]
    const float* Wr     = (const float*)d_in[5];  // [H]
    const float* br     = (const float*)d_in[6];  // scalar
    const float* Wg     = (const float*)d_in[7];  // [2,ET]
    const float* bg     = (const float*)d_in[8];  // [2]

    float* out      = (float*)d_out;
    float* out_gate = out + (out_size - BB * TT * 2);

    proj_gate_kernel<<<GEMM_TILES + 2, 128>>>(source, target, Ws, Wt, Wg, bg, out_gate);
    attn_kernel<<<dim3(SS / 64, TT / 32, BB * NHS), 256>>>(Wr, maskF, br, out);
}